// round 12
// baseline (speedup 1.0000x reference)
#include <cuda_runtime.h>
#include <math.h>

#define NN 50000
#define EE 400000
#define FF 32
#define HALF_E (EE / 2)
#define QE (EE / 4)

typedef unsigned long long ull;

// ---------------- scratch ----------------
// e-feature buffers TRANSPOSED: [FF][EE], element (k, e) at k*EE + e
__device__ __align__(128) float g_e1[(size_t)EE * FF];
__device__ __align__(128) float g_e2[(size_t)EE * FF];
__device__ __align__(128) float g_e3[(size_t)EE * FF];
__device__ __align__(128) float g_acc1[(size_t)NN * FF];
__device__ __align__(128) float g_acc2[(size_t)NN * FF];
__device__ __align__(128) float g_acc3[(size_t)NN * FF];
__device__ __align__(128) float g_uv[(size_t)NN * 64];
__device__ __align__(128) float g_cnt[NN];
__device__ __align__(16) float g_wx[FF * 4];
__device__ __align__(16) float g_bx[4];
__device__ __align__(16) float g_wz[FF];
__device__ float g_bz;

// ---------------- f32x2 helpers ----------------
__device__ __forceinline__ void ffma2(ull& d, ull a, ull b) {
    asm("fma.rn.f32x2 %0, %1, %2, %0;" : "+l"(d) : "l"(a), "l"(b));
}
__device__ __forceinline__ ull pk2(float v) {
    ull r;
    asm("mov.b64 %0, {%1, %1};" : "=l"(r) : "f"(v));
    return r;
}
union V32 {
    float f[FF];
    ull u[FF / 2];
};

__device__ __forceinline__ void cpsh(float* dst, const float* src, int n, int tid, int nt) {
    for (int i = tid; i < n; i += nt) dst[i] = src[i];
}
__device__ __forceinline__ void ldbias(V32& h, const float* __restrict__ b) {
#pragma unroll
    for (int j = 0; j < FF; j++) h.f[j] = b[j];
}
__device__ __forceinline__ void relu32(V32& h) {
#pragma unroll
    for (int j = 0; j < FF; j++) h.f[j] = fmaxf(h.f[j], 0.f);
}
__device__ __forceinline__ void red4(float* __restrict__ a, float x, float y, float z, float w) {
    asm volatile("red.global.add.v4.f32 [%0], {%1, %2, %3, %4};" ::"l"(a), "f"(x), "f"(y),
                 "f"(z), "f"(w)
                 : "memory");
}
__device__ __forceinline__ void scatter32(float* __restrict__ acc, const V32& o) {
#pragma unroll
    for (int j = 0; j < FF; j += 4) red4(acc + j, o.f[j], o.f[j + 1], o.f[j + 2], o.f[j + 3]);
}

__device__ __forceinline__ void fmarow1(V32& h, ull v, const float* __restrict__ wr) {
#pragma unroll
    for (int j = 0; j < 8; j++) {
        ulonglong2 w = *(const ulonglong2*)(wr + j * 4);
        ffma2(h.u[2 * j + 0], v, w.x);
        ffma2(h.u[2 * j + 1], v, w.y);
    }
}
__device__ __forceinline__ void fmarow2p(V32& h0, V32& h1, ull v0, ull v1,
                                         const float* __restrict__ wr) {
#pragma unroll
    for (int j = 0; j < 8; j++) {
        ulonglong2 w = *(const ulonglong2*)(wr + j * 4);
        ffma2(h0.u[2 * j + 0], v0, w.x);
        ffma2(h0.u[2 * j + 1], v0, w.y);
        ffma2(h1.u[2 * j + 0], v1, w.x);
        ffma2(h1.u[2 * j + 1], v1, w.y);
    }
}
// quad row: 1 weight load feeds 4 edges
__device__ __forceinline__ void fmarow4(V32& h0, V32& h1, V32& h2, V32& h3, ull v0, ull v1,
                                        ull v2, ull v3, const float* __restrict__ wr) {
#pragma unroll
    for (int j = 0; j < 8; j++) {
        ulonglong2 w = *(const ulonglong2*)(wr + j * 4);
        ffma2(h0.u[2 * j], v0, w.x);
        ffma2(h0.u[2 * j + 1], v0, w.y);
        ffma2(h1.u[2 * j], v1, w.x);
        ffma2(h1.u[2 * j + 1], v1, w.y);
        ffma2(h2.u[2 * j], v2, w.x);
        ffma2(h2.u[2 * j + 1], v2, w.y);
        ffma2(h3.u[2 * j], v3, w.x);
        ffma2(h3.u[2 * j + 1], v3, w.y);
    }
}
// quad segment from transposed buffer: per k one coalesced LDG.128 (4 edges)
__device__ __forceinline__ void seg32qT(V32& h0, V32& h1, V32& h2, V32& h3,
                                        const float* __restrict__ gT, int e0,
                                        const float* __restrict__ ws) {
    const float* p = gT + e0;
#pragma unroll
    for (int k = 0; k < FF; k++) {
        float4 v = *(const float4*)(p + (size_t)k * EE);
        fmarow4(h0, h1, h2, h3, pk2(v.x), pk2(v.y), pk2(v.z), pk2(v.w), ws + k * FF);
    }
}
__device__ __forceinline__ void layer2p(V32& o0, V32& o1, const V32& h0, const V32& h1,
                                        const float* __restrict__ sw1,
                                        const float* __restrict__ sb1) {
    ldbias(o0, sb1);
    ldbias(o1, sb1);
#pragma unroll
    for (int k = 0; k < FF; k++) fmarow2p(o0, o1, pk2(h0.f[k]), pk2(h1.f[k]), sw1 + k * FF);
}
__device__ __forceinline__ void store_relu2T(float* __restrict__ gT, int e0, const V32& o0,
                                             const V32& o1) {
    float* p = gT + e0;
#pragma unroll
    for (int j = 0; j < FF; j++) {
        float2 t = make_float2(fmaxf(o0.f[j], 0.f), fmaxf(o1.f[j], 0.f));
        *(float2*)(p + (size_t)j * EE) = t;
    }
}
__device__ __forceinline__ void uvinit(V32& h, int r, int c) {
    const float* U = g_uv + (size_t)r * 64;
    const float* V = g_uv + (size_t)c * 64 + 32;
#pragma unroll
    for (int j = 0; j < FF; j += 4) {
        float4 a = *(const float4*)(U + j);
        float4 b = *(const float4*)(V + j);
        h.f[j + 0] = a.x + b.x;
        h.f[j + 1] = a.y + b.y;
        h.f[j + 2] = a.z + b.z;
        h.f[j + 3] = a.w + b.w;
    }
}

// ---------------- init / head fold ----------------
__global__ void k_init(const float* __restrict__ beta, float* __restrict__ out) {
    int i = blockIdx.x * blockDim.x + threadIdx.x;
    if (i < NN * FF) {
        g_acc1[i] = 0.f;
        g_acc2[i] = 0.f;
        g_acc3[i] = 0.f;
    }
    if (i < NN) g_cnt[i] = 0.f;
    if (i < 3 * NN) out[(size_t)5 * EE + i] = beta[i];
}
__global__ void k_headfold(const float* __restrict__ wl01, const float* __restrict__ bl01,
                           const float* __restrict__ wl02, const float* __restrict__ bl02,
                           const float* __restrict__ wl1, const float* __restrict__ bl1,
                           const float* __restrict__ wl2, const float* __restrict__ bl2) {
    int t = threadIdx.x;
    if (t < 128) {
        int k = t >> 2, j = t & 3;
        float s = 0.f;
#pragma unroll
        for (int m = 0; m < FF; m++) s += wl01[k * FF + m] * wl1[m * 4 + j];
        g_wx[k * 4 + j] = s;
    }
    if (t < 4) {
        float s = bl1[t];
#pragma unroll
        for (int m = 0; m < FF; m++) s += bl01[m] * wl1[m * 4 + t];
        g_bx[t] = s;
    }
    if (t >= 128 && t < 160) {
        int k = t - 128;
        float s = 0.f;
#pragma unroll
        for (int m = 0; m < FF; m++) s += wl02[k * FF + m] * wl2[m];
        g_wz[k] = s;
    }
    if (t == 160) {
        float s = bl2[0];
#pragma unroll
        for (int m = 0; m < FF; m++) s += bl02[m] * wl2[m];
        g_bz = s;
    }
}

// ---------------- node projection (unchanged, R10 form) ----------------
template <int KP>
__global__ __launch_bounds__(256) void k_node(const float* __restrict__ acca,
                                              const float* __restrict__ accb,
                                              const float* __restrict__ W0,
                                              const float* __restrict__ b0) {
    __shared__ __align__(16) float s_w[2 * KP * FF];
    __shared__ __align__(16) float s_b[FF];
    int tid = threadIdx.x;

    int n = blockIdx.x * 128 + (tid & 127);
    float cnt = (n < NN) ? g_cnt[n] : 1.0f;

    cpsh(s_w, W0, 2 * KP * FF, tid, 256);
    cpsh(s_b, b0, FF, tid, 256);
    __syncthreads();

    int isV = tid >> 7;
    if (n >= NN) return;

    float inv = 1.0f / fmaxf(cnt, 1.0f);
    const float* ws = s_w + (isV ? KP * FF : 0);

    V32 acc;
    if (isV) {
#pragma unroll
        for (int j = 0; j < FF; j++) acc.f[j] = 0.f;
    } else {
        ldbias(acc, s_b);
    }

    const float* xpa = acca + (size_t)n * FF;
#pragma unroll
    for (int k4 = 0; k4 < 8; k4++) {
        float4 xv = *(const float4*)(xpa + k4 * 4);
        xv.x = fmaxf(xv.x, 0.f) * inv;
        xv.y = fmaxf(xv.y, 0.f) * inv;
        xv.z = fmaxf(xv.z, 0.f) * inv;
        xv.w = fmaxf(xv.w, 0.f) * inv;
        int k = k4 * 4;
        fmarow1(acc, pk2(xv.x), ws + (k + 0) * FF);
        fmarow1(acc, pk2(xv.y), ws + (k + 1) * FF);
        fmarow1(acc, pk2(xv.z), ws + (k + 2) * FF);
        fmarow1(acc, pk2(xv.w), ws + (k + 3) * FF);
    }
    if (KP == 64) {
        const float* xpb = accb + (size_t)n * FF;
#pragma unroll
        for (int k4 = 0; k4 < 8; k4++) {
            float4 xv = *(const float4*)(xpb + k4 * 4);
            xv.x = fmaxf(xv.x, 0.f) * inv;
            xv.y = fmaxf(xv.y, 0.f) * inv;
            xv.z = fmaxf(xv.z, 0.f) * inv;
            xv.w = fmaxf(xv.w, 0.f) * inv;
            int k = 32 + k4 * 4;
            fmarow1(acc, pk2(xv.x), ws + (k + 0) * FF);
            fmarow1(acc, pk2(xv.y), ws + (k + 1) * FF);
            fmarow1(acc, pk2(xv.z), ws + (k + 2) * FF);
            fmarow1(acc, pk2(xv.w), ws + (k + 3) * FF);
        }
    }

    float* up = g_uv + (size_t)n * 64 + isV * 32;
#pragma unroll
    for (int j = 0; j < FF; j += 4) *(float4*)(up + j) = *(float4*)(acc.f + j);
}

// ---------------- conv1 (pair; unchanged R10/R11 form) ----------------
__global__ __launch_bounds__(128) void k_conv1(const float* __restrict__ ea,
                                               const int* __restrict__ eidx,
                                               const float* __restrict__ w10,
                                               const float* __restrict__ b10,
                                               const float* __restrict__ w11,
                                               const float* __restrict__ b11) {
    __shared__ __align__(16) float s_w0[4 * FF];
    __shared__ __align__(16) float s_b0[FF];
    __shared__ __align__(16) float s_w1[FF * FF];
    __shared__ __align__(16) float s_b1[FF];
    int tid = threadIdx.x, nt = blockDim.x;

    int p = blockIdx.x * nt + tid;
    bool act = p < HALF_E;
    int e0 = 2 * p, e1 = 2 * p + 1;
    float4 a0, a1;
    int r0 = 0, r1 = 0;
    if (act) {
        a0 = *(const float4*)(ea + (size_t)e0 * 4);
        a1 = *(const float4*)(ea + (size_t)e1 * 4);
        r0 = eidx[e0];
        r1 = eidx[e1];
    }

    cpsh(s_w0, w10, 4 * FF, tid, nt);
    cpsh(s_b0, b10, FF, tid, nt);
    cpsh(s_w1, w11, FF * FF, tid, nt);
    cpsh(s_b1, b11, FF, tid, nt);
    __syncthreads();
    if (!act) return;

    V32 h0, h1;
    ldbias(h0, s_b0);
    ldbias(h1, s_b0);
    fmarow2p(h0, h1, pk2(a0.x), pk2(a1.x), s_w0);
    fmarow2p(h0, h1, pk2(a0.y), pk2(a1.y), s_w0 + FF);
    fmarow2p(h0, h1, pk2(a0.z), pk2(a1.z), s_w0 + 2 * FF);
    fmarow2p(h0, h1, pk2(a0.w), pk2(a1.w), s_w0 + 3 * FF);
    relu32(h0);
    relu32(h1);

    V32 o0, o1;
    layer2p(o0, o1, h0, h1, s_w1, s_b1);

    scatter32(g_acc1 + (size_t)r0 * FF, o0);
    scatter32(g_acc1 + (size_t)r1 * FF, o1);
    atomicAdd(&g_cnt[r0], 1.0f);
    atomicAdd(&g_cnt[r1], 1.0f);
    store_relu2T(g_e1, e0, o0, o1);
}

// ================= quad edge kernels with smem h-spill =================
// 64-thread blocks, 4 edges/thread. Hs slot: (k*64 + tid) float4.

#define QT 64

// ---------------- edge2 quad: layer1 rows = [ea(4), e1(32)] ----------------
// smem floats: w0e[36*32]=1152, w1 1024, b1 32, Hs 8192  => 10400 floats
#define E2_W1 1152
#define E2_B1 2176
#define E2_HS 2208
#define E2_TOT 10400

__global__ __launch_bounds__(QT) void k_edge2q(const float* __restrict__ ea,
                                               const int* __restrict__ eidx,
                                               const float* __restrict__ w20,
                                               const float* __restrict__ w21,
                                               const float* __restrict__ b21) {
    extern __shared__ float sm[];
    float* s_w0e = sm;
    float* s_w1 = sm + E2_W1;
    float* s_b1 = sm + E2_B1;
    float* Hs = sm + E2_HS;
    int tid = threadIdx.x;

    int p = blockIdx.x * QT + tid;
    bool act = p < QE;
    int e0 = 4 * p;
    int r[4], c[4];
    float4 a[4];
    V32 h0, h1, h2, h3;
    if (act) {
#pragma unroll
        for (int e = 0; e < 4; e++) {
            r[e] = eidx[e0 + e];
            c[e] = eidx[EE + e0 + e];
            a[e] = *(const float4*)(ea + (size_t)(e0 + e) * 4);
        }
        uvinit(h0, r[0], c[0]);
        uvinit(h1, r[1], c[1]);
        uvinit(h2, r[2], c[2]);
        uvinit(h3, r[3], c[3]);
    }

    cpsh(s_w0e, w20 + 64 * FF, 36 * FF, tid, QT);
    cpsh(s_w1, w21, FF * FF, tid, QT);
    cpsh(s_b1, b21, FF, tid, QT);
    __syncthreads();
    if (!act) return;

    // phase A: layer1
    fmarow4(h0, h1, h2, h3, pk2(a[0].x), pk2(a[1].x), pk2(a[2].x), pk2(a[3].x), s_w0e);
    fmarow4(h0, h1, h2, h3, pk2(a[0].y), pk2(a[1].y), pk2(a[2].y), pk2(a[3].y), s_w0e + FF);
    fmarow4(h0, h1, h2, h3, pk2(a[0].z), pk2(a[1].z), pk2(a[2].z), pk2(a[3].z),
            s_w0e + 2 * FF);
    fmarow4(h0, h1, h2, h3, pk2(a[0].w), pk2(a[1].w), pk2(a[2].w), pk2(a[3].w),
            s_w0e + 3 * FF);
    seg32qT(h0, h1, h2, h3, g_e1, e0, s_w0e + 4 * FF);
    relu32(h0);
    relu32(h1);
    relu32(h2);
    relu32(h3);

    // spill relu(h) to smem (thread-private, conflict-free)
    float* hp = Hs + tid * 4;
#pragma unroll
    for (int k = 0; k < FF; k++)
        *(float4*)(hp + k * (QT * 4)) = make_float4(h0.f[k], h1.f[k], h2.f[k], h3.f[k]);

    // phase B: layer2 from smem
    V32 o0, o1, o2, o3;
    ldbias(o0, s_b1);
    ldbias(o1, s_b1);
    ldbias(o2, s_b1);
    ldbias(o3, s_b1);
#pragma unroll
    for (int k = 0; k < FF; k++) {
        float4 hv = *(const float4*)(hp + k * (QT * 4));
        fmarow4(o0, o1, o2, o3, pk2(hv.x), pk2(hv.y), pk2(hv.z), pk2(hv.w), s_w1 + k * FF);
    }

    scatter32(g_acc2 + (size_t)r[0] * FF, o0);
    scatter32(g_acc2 + (size_t)r[1] * FF, o1);
    scatter32(g_acc2 + (size_t)r[2] * FF, o2);
    scatter32(g_acc2 + (size_t)r[3] * FF, o3);
    float* pT = g_e2 + e0;
#pragma unroll
    for (int j = 0; j < FF; j++) {
        *(float4*)(pT + (size_t)j * EE) =
            make_float4(fmaxf(o0.f[j], 0.f), fmaxf(o1.f[j], 0.f), fmaxf(o2.f[j], 0.f),
                        fmaxf(o3.f[j], 0.f));
    }
}

// ---------------- edge3 quad: layer1 rows = [e2(32), e1(32)] ----------------
// smem floats: w0e 2048, w1 1024, b1 32, Hs 8192 => 11296
#define E3_W1 2048
#define E3_B1 3072
#define E3_HS 3104
#define E3_TOT 11296

__global__ __launch_bounds__(QT) void k_edge3q(const int* __restrict__ eidx,
                                               const float* __restrict__ w30,
                                               const float* __restrict__ w31,
                                               const float* __restrict__ b31) {
    extern __shared__ float sm[];
    float* s_w0e = sm;
    float* s_w1 = sm + E3_W1;
    float* s_b1 = sm + E3_B1;
    float* Hs = sm + E3_HS;
    int tid = threadIdx.x;

    int p = blockIdx.x * QT + tid;
    bool act = p < QE;
    int e0 = 4 * p;
    int r[4], c[4];
    V32 h0, h1, h2, h3;
    if (act) {
#pragma unroll
        for (int e = 0; e < 4; e++) {
            r[e] = eidx[e0 + e];
            c[e] = eidx[EE + e0 + e];
        }
        uvinit(h0, r[0], c[0]);
        uvinit(h1, r[1], c[1]);
        uvinit(h2, r[2], c[2]);
        uvinit(h3, r[3], c[3]);
    }

    cpsh(s_w0e, w30 + 128 * FF, 64 * FF, tid, QT);
    cpsh(s_w1, w31, FF * FF, tid, QT);
    cpsh(s_b1, b31, FF, tid, QT);
    __syncthreads();
    if (!act) return;

    seg32qT(h0, h1, h2, h3, g_e2, e0, s_w0e);
    seg32qT(h0, h1, h2, h3, g_e1, e0, s_w0e + 32 * FF);
    relu32(h0);
    relu32(h1);
    relu32(h2);
    relu32(h3);

    float* hp = Hs + tid * 4;
#pragma unroll
    for (int k = 0; k < FF; k++)
        *(float4*)(hp + k * (QT * 4)) = make_float4(h0.f[k], h1.f[k], h2.f[k], h3.f[k]);

    V32 o0, o1, o2, o3;
    ldbias(o0, s_b1);
    ldbias(o1, s_b1);
    ldbias(o2, s_b1);
    ldbias(o3, s_b1);
#pragma unroll
    for (int k = 0; k < FF; k++) {
        float4 hv = *(const float4*)(hp + k * (QT * 4));
        fmarow4(o0, o1, o2, o3, pk2(hv.x), pk2(hv.y), pk2(hv.z), pk2(hv.w), s_w1 + k * FF);
    }

    scatter32(g_acc3 + (size_t)r[0] * FF, o0);
    scatter32(g_acc3 + (size_t)r[1] * FF, o1);
    scatter32(g_acc3 + (size_t)r[2] * FF, o2);
    scatter32(g_acc3 + (size_t)r[3] * FF, o3);
    float* pT = g_e3 + e0;
#pragma unroll
    for (int j = 0; j < FF; j++) {
        *(float4*)(pT + (size_t)j * EE) =
            make_float4(fmaxf(o0.f[j], 0.f), fmaxf(o1.f[j], 0.f), fmaxf(o2.f[j], 0.f),
                        fmaxf(o3.f[j], 0.f));
    }
}

// ---------------- edge4 quad + folded heads ----------------
// smem floats: w0e 2048, w1 1024, b1 32, wx 128, wz 32, bx 4, bz 1, pad 3, Hs 8192
#define E4_W1 2048
#define E4_B1 3072
#define E4_WX 3104
#define E4_WZ 3232
#define E4_BX 3264
#define E4_BZ 3268
#define E4_HS 3272
#define E4_TOT 11464

__global__ __launch_bounds__(QT) void k_edge4q(const float* __restrict__ ea,
                                               const int* __restrict__ eidx,
                                               const float* __restrict__ w40,
                                               const float* __restrict__ w41,
                                               const float* __restrict__ b41,
                                               float* __restrict__ out) {
    extern __shared__ float sm[];
    float* s_w0e = sm;
    float* s_w1 = sm + E4_W1;
    float* s_b1 = sm + E4_B1;
    float* s_wx = sm + E4_WX;
    float* s_wz = sm + E4_WZ;
    float* s_bx = sm + E4_BX;
    float* s_bz = sm + E4_BZ;
    float* Hs = sm + E4_HS;
    int tid = threadIdx.x;

    int p = blockIdx.x * QT + tid;
    bool act = p < QE;
    int e0 = 4 * p;
    int r[4], c[4];
    float4 a[4];
    V32 h0, h1, h2, h3;
    if (act) {
#pragma unroll
        for (int e = 0; e < 4; e++) {
            r[e] = eidx[e0 + e];
            c[e] = eidx[EE + e0 + e];
            a[e] = *(const float4*)(ea + (size_t)(e0 + e) * 4);
        }
        uvinit(h0, r[0], c[0]);
        uvinit(h1, r[1], c[1]);
        uvinit(h2, r[2], c[2]);
        uvinit(h3, r[3], c[3]);
    }

    cpsh(s_w0e, w40 + 128 * FF, 64 * FF, tid, QT);
    cpsh(s_w1, w41, FF * FF, tid, QT);
    cpsh(s_b1, b41, FF, tid, QT);
    cpsh(s_wx, g_wx, FF * 4, tid, QT);
    cpsh(s_wz, g_wz, FF, tid, QT);
    if (tid < 4) s_bx[tid] = g_bx[tid];
    if (tid == 0) s_bz[0] = g_bz;
    __syncthreads();
    if (!act) return;

    seg32qT(h0, h1, h2, h3, g_e3, e0, s_w0e);
    seg32qT(h0, h1, h2, h3, g_e2, e0, s_w0e + 32 * FF);
    relu32(h0);
    relu32(h1);
    relu32(h2);
    relu32(h3);

    float* hp = Hs + tid * 4;
#pragma unroll
    for (int k = 0; k < FF; k++)
        *(float4*)(hp + k * (QT * 4)) = make_float4(h0.f[k], h1.f[k], h2.f[k], h3.f[k]);

    V32 o0, o1, o2, o3;
    ldbias(o0, s_b1);
    ldbias(o1, s_b1);
    ldbias(o2, s_b1);
    ldbias(o3, s_b1);
#pragma unroll
    for (int k = 0; k < FF; k++) {
        float4 hv = *(const float4*)(hp + k * (QT * 4));
        fmarow4(o0, o1, o2, o3, pk2(hv.x), pk2(hv.y), pk2(hv.z), pk2(hv.w), s_w1 + k * FF);
    }
    relu32(o0);  // o = relu(e4)
    relu32(o1);
    relu32(o2);
    relu32(o3);

    // folded heads, all 4 edges in one k-loop (weights hoisted)
    float X0[4], X1[4], X2[4], X3[4], Z[4];
#pragma unroll
    for (int e = 0; e < 4; e++) {
        X0[e] = s_bx[0] + a[e].x;
        X1[e] = s_bx[1] + a[e].y;
        X2[e] = s_bx[2] + a[e].z;
        X3[e] = s_bx[3] + a[e].w;
        Z[e] = s_bz[0];
    }
#pragma unroll
    for (int k = 0; k < FF; k++) {
        float4 w = *(const float4*)(s_wx + k * 4);
        float wzk = s_wz[k];
        float v0 = o0.f[k], v1 = o1.f[k], v2 = o2.f[k], v3 = o3.f[k];
        X0[0] += v0 * w.x;
        X1[0] += v0 * w.y;
        X2[0] += v0 * w.z;
        X3[0] += v0 * w.w;
        Z[0] += v0 * wzk;
        X0[1] += v1 * w.x;
        X1[1] += v1 * w.y;
        X2[1] += v1 * w.z;
        X3[1] += v1 * w.w;
        Z[1] += v1 * wzk;
        X0[2] += v2 * w.x;
        X1[2] += v2 * w.y;
        X2[2] += v2 * w.z;
        X3[2] += v2 * w.w;
        Z[2] += v2 * wzk;
        X0[3] += v3 * w.x;
        X1[3] += v3 * w.y;
        X2[3] += v3 * w.z;
        X3[3] += v3 * w.w;
        Z[3] += v3 * wzk;
    }
#pragma unroll
    for (int e = 0; e < 4; e++) {
        float nrm = sqrtf(X0[e] * X0[e] + X1[e] * X1[e] + X2[e] * X2[e] + X3[e] * X3[e]);
        float inv = 1.0f / fmaxf(nrm, 1e-12f);
        *(float4*)(out + (size_t)EE + (size_t)(e0 + e) * 4) =
            make_float4(X0[e] * inv, X1[e] * inv, X2[e] * inv, X3[e] * inv);
        out[e0 + e] = 1.0f / (1.0f + expf(-Z[e]));
    }
}

// ---------------- launch ----------------
extern "C" void kernel_launch(void* const* d_in, const int* in_sizes, int n_in,
                              void* d_out, int out_size) {
    const int* eidx = (const int*)d_in[1];
    const float* ea = (const float*)d_in[2];
    const float* beta = (const float*)d_in[3];
    const float* w10 = (const float*)d_in[4];
    const float* b10 = (const float*)d_in[5];
    const float* w11 = (const float*)d_in[6];
    const float* b11 = (const float*)d_in[7];
    const float* w20 = (const float*)d_in[8];
    const float* b20 = (const float*)d_in[9];
    const float* w21 = (const float*)d_in[10];
    const float* b21 = (const float*)d_in[11];
    const float* w30 = (const float*)d_in[12];
    const float* b30 = (const float*)d_in[13];
    const float* w31 = (const float*)d_in[14];
    const float* b31 = (const float*)d_in[15];
    const float* w40 = (const float*)d_in[16];
    const float* b40 = (const float*)d_in[17];
    const float* w41 = (const float*)d_in[18];
    const float* b41 = (const float*)d_in[19];
    const float* wl01 = (const float*)d_in[20];
    const float* bl01 = (const float*)d_in[21];
    const float* wl02 = (const float*)d_in[22];
    const float* bl02 = (const float*)d_in[23];
    const float* wl1 = (const float*)d_in[24];
    const float* bl1 = (const float*)d_in[25];
    const float* wl2 = (const float*)d_in[26];
    const float* bl2 = (const float*)d_in[27];
    float* out = (float*)d_out;

    float *acc1p, *acc2p, *acc3p;
    cudaGetSymbolAddress((void**)&acc1p, g_acc1);
    cudaGetSymbolAddress((void**)&acc2p, g_acc2);
    cudaGetSymbolAddress((void**)&acc3p, g_acc3);

    static int attr_done = 0;
    if (!attr_done) {
        cudaFuncSetAttribute(k_edge2q, cudaFuncAttributeMaxDynamicSharedMemorySize,
                             E2_TOT * 4);
        cudaFuncSetAttribute(k_edge3q, cudaFuncAttributeMaxDynamicSharedMemorySize,
                             E3_TOT * 4);
        cudaFuncSetAttribute(k_edge4q, cudaFuncAttributeMaxDynamicSharedMemorySize,
                             E4_TOT * 4);
        attr_done = 1;
    }

    const int T = 256;
    const int gridNF = (NN * FF + T - 1) / T;
    const int TB = 128;
    const int gridP = (HALF_E + TB - 1) / TB;
    const int gridN = (NN + 127) / 128;
    const int gridQ = (QE + QT - 1) / QT;

    k_init<<<gridNF, T>>>(beta, out);
    k_headfold<<<1, 192>>>(wl01, bl01, wl02, bl02, wl1, bl1, wl2, bl2);
    k_conv1<<<gridP, TB>>>(ea, eidx, w10, b10, w11, b11);

    k_node<32><<<gridN, 256>>>(acc1p, nullptr, w20, b20);
    k_edge2q<<<gridQ, QT, E2_TOT * 4>>>(ea, eidx, w20, w21, b21);

    k_node<64><<<gridN, 256>>>(acc2p, acc1p, w30, b30);
    k_edge3q<<<gridQ, QT, E3_TOT * 4>>>(eidx, w30, w31, b31);

    k_node<64><<<gridN, 256>>>(acc3p, acc2p, w40, b40);
    k_edge4q<<<gridQ, QT, E4_TOT * 4>>>(ea, eidx, w40, w41, b41, out);
}

// round 13
// speedup vs baseline: 1.2785x; 1.2785x over previous
#include <cuda_runtime.h>
#include <math.h>

#define NN 50000
#define EE 400000
#define FF 32
#define HALF_E (EE / 2)

typedef unsigned long long ull;

// ---------------- scratch ----------------
// e-feature buffers TRANSPOSED: [FF][EE]
__device__ __align__(128) float g_e1[(size_t)EE * FF];
__device__ __align__(128) float g_e2[(size_t)EE * FF];
__device__ __align__(128) float g_e3[(size_t)EE * FF];
__device__ __align__(128) float g_acc1[(size_t)NN * FF];
__device__ __align__(128) float g_acc2[(size_t)NN * FF];
__device__ __align__(128) float g_acc3[(size_t)NN * FF];
__device__ __align__(128) float g_uv[(size_t)NN * 64];
__device__ __align__(128) float g_cnt[NN];
__device__ __align__(128) float g_wpack[9800];

// ---------------- packed constant weights ----------------
#define O_W10 0
#define O_B10 128
#define O_W11 160
#define O_B11 1184
#define O_W20E 1216
#define O_W21 2368
#define O_B21 3392
#define O_W30E 3424
#define O_W31 5472
#define O_B31 6496
#define O_W40E 6528
#define O_W41 8576
#define O_B41 9600
#define O_WX 9632
#define O_WZ 9760
#define O_BX 9792
#define O_BZ 9796
#define PACK_N 9797

__constant__ float c_pack[9800];

// ---------------- f32x2 helpers ----------------
__device__ __forceinline__ void ffma2(ull& d, ull a, ull b) {
    asm("fma.rn.f32x2 %0, %1, %2, %0;" : "+l"(d) : "l"(a), "l"(b));
}
__device__ __forceinline__ ull pk2(float v) {
    ull r;
    asm("mov.b64 %0, {%1, %1};" : "=l"(r) : "f"(v));
    return r;
}
union V32 {
    float f[FF];
    ull u[FF / 2];
};

__device__ __forceinline__ void cpsh(float* dst, const float* src, int n, int tid, int nt) {
    for (int i = tid; i < n; i += nt) dst[i] = src[i];
}
__device__ __forceinline__ void relu32(V32& h) {
#pragma unroll
    for (int j = 0; j < FF; j++) h.f[j] = fmaxf(h.f[j], 0.f);
}
__device__ __forceinline__ void red4(float* __restrict__ a, float x, float y, float z, float w) {
    asm volatile("red.global.add.v4.f32 [%0], {%1, %2, %3, %4};" ::"l"(a), "f"(x), "f"(y),
                 "f"(z), "f"(w)
                 : "memory");
}
__device__ __forceinline__ void scatter32(float* __restrict__ acc, const V32& o) {
#pragma unroll
    for (int j = 0; j < FF; j += 4) red4(acc + j, o.f[j], o.f[j + 1], o.f[j + 2], o.f[j + 3]);
}

// ---- constant-weight math ----
__device__ __forceinline__ void ldbiasc(V32& h, int bo) {
#pragma unroll
    for (int j = 0; j < FF; j++) h.f[j] = c_pack[bo + j];
}
// h{0,1} += v{0,1} * c_pack[wo .. wo+31]
__device__ __forceinline__ void fmarow2c(V32& h0, V32& h1, ull v0, ull v1, int wo) {
#pragma unroll
    for (int j = 0; j < 8; j++) {
        ulonglong2 w = *(const ulonglong2*)(c_pack + wo + j * 4);
        ffma2(h0.u[2 * j + 0], v0, w.x);
        ffma2(h0.u[2 * j + 1], v0, w.y);
        ffma2(h1.u[2 * j + 0], v1, w.x);
        ffma2(h1.u[2 * j + 1], v1, w.y);
    }
}
// 32-row segment from transposed feature buffer
__device__ __forceinline__ void seg32pTc(V32& h0, V32& h1, const float* __restrict__ gT,
                                         int e0, int wo) {
    const float* p = gT + e0;
#pragma unroll
    for (int k = 0; k < FF; k++) {
        float2 v = *(const float2*)(p + (size_t)k * EE);
        fmarow2c(h0, h1, pk2(v.x), pk2(v.y), wo + k * FF);
    }
}
__device__ __forceinline__ void layer2c(V32& o0, V32& o1, const V32& h0, const V32& h1,
                                        int wo, int bo) {
    ldbiasc(o0, bo);
    ldbiasc(o1, bo);
#pragma unroll
    for (int k = 0; k < FF; k++) fmarow2c(o0, o1, pk2(h0.f[k]), pk2(h1.f[k]), wo + k * FF);
}
__device__ __forceinline__ void store_relu2T(float* __restrict__ gT, int e0, const V32& o0,
                                             const V32& o1) {
    float* p = gT + e0;
#pragma unroll
    for (int j = 0; j < FF; j++) {
        float2 t = make_float2(fmaxf(o0.f[j], 0.f), fmaxf(o1.f[j], 0.f));
        *(float2*)(p + (size_t)j * EE) = t;
    }
}
__device__ __forceinline__ void uvinit(V32& h, int r, int c) {
    const float* U = g_uv + (size_t)r * 64;
    const float* V = g_uv + (size_t)c * 64 + 32;
#pragma unroll
    for (int j = 0; j < FF; j += 4) {
        float4 a = *(const float4*)(U + j);
        float4 b = *(const float4*)(V + j);
        h.f[j + 0] = a.x + b.x;
        h.f[j + 1] = a.y + b.y;
        h.f[j + 2] = a.z + b.z;
        h.f[j + 3] = a.w + b.w;
    }
}
__device__ __forceinline__ void ldbias_s(V32& h, const float* __restrict__ b) {
#pragma unroll
    for (int j = 0; j < FF; j++) h.f[j] = b[j];
}
__device__ __forceinline__ void fmarow1(V32& h, ull v, const float* __restrict__ wr) {
#pragma unroll
    for (int j = 0; j < 8; j++) {
        ulonglong2 w = *(const ulonglong2*)(wr + j * 4);
        ffma2(h.u[2 * j + 0], v, w.x);
        ffma2(h.u[2 * j + 1], v, w.y);
    }
}

// ---------------- init ----------------
__global__ void k_init(const float* __restrict__ beta, float* __restrict__ out) {
    int i = blockIdx.x * blockDim.x + threadIdx.x;
    if (i < NN * FF) {
        g_acc1[i] = 0.f;
        g_acc2[i] = 0.f;
        g_acc3[i] = 0.f;
    }
    if (i < NN) g_cnt[i] = 0.f;
    if (i < 3 * NN) out[(size_t)5 * EE + i] = beta[i];
}

// ---------------- pack: gather weights + head fold into g_wpack ----------------
__global__ void k_pack(const float* __restrict__ w10, const float* __restrict__ b10,
                       const float* __restrict__ w11, const float* __restrict__ b11,
                       const float* __restrict__ w20, const float* __restrict__ w21,
                       const float* __restrict__ b21, const float* __restrict__ w30,
                       const float* __restrict__ w31, const float* __restrict__ b31,
                       const float* __restrict__ w40, const float* __restrict__ w41,
                       const float* __restrict__ b41, const float* __restrict__ wl01,
                       const float* __restrict__ bl01, const float* __restrict__ wl02,
                       const float* __restrict__ bl02, const float* __restrict__ wl1,
                       const float* __restrict__ bl1, const float* __restrict__ wl2,
                       const float* __restrict__ bl2) {
    int t = threadIdx.x;
    const int NT = 256;
    for (int i = t; i < 128; i += NT) g_wpack[O_W10 + i] = w10[i];
    for (int i = t; i < 32; i += NT) g_wpack[O_B10 + i] = b10[i];
    for (int i = t; i < 1024; i += NT) g_wpack[O_W11 + i] = w11[i];
    for (int i = t; i < 32; i += NT) g_wpack[O_B11 + i] = b11[i];
    for (int i = t; i < 36 * 32; i += NT) g_wpack[O_W20E + i] = w20[64 * 32 + i];
    for (int i = t; i < 1024; i += NT) g_wpack[O_W21 + i] = w21[i];
    for (int i = t; i < 32; i += NT) g_wpack[O_B21 + i] = b21[i];
    for (int i = t; i < 64 * 32; i += NT) g_wpack[O_W30E + i] = w30[128 * 32 + i];
    for (int i = t; i < 1024; i += NT) g_wpack[O_W31 + i] = w31[i];
    for (int i = t; i < 32; i += NT) g_wpack[O_B31 + i] = b31[i];
    for (int i = t; i < 64 * 32; i += NT) g_wpack[O_W40E + i] = w40[128 * 32 + i];
    for (int i = t; i < 1024; i += NT) g_wpack[O_W41 + i] = w41[i];
    for (int i = t; i < 32; i += NT) g_wpack[O_B41 + i] = b41[i];
    // head fold
    if (t < 128) {
        int k = t >> 2, j = t & 3;
        float s = 0.f;
#pragma unroll
        for (int m = 0; m < FF; m++) s += wl01[k * FF + m] * wl1[m * 4 + j];
        g_wpack[O_WX + k * 4 + j] = s;
    }
    if (t < 4) {
        float s = bl1[t];
#pragma unroll
        for (int m = 0; m < FF; m++) s += bl01[m] * wl1[m * 4 + t];
        g_wpack[O_BX + t] = s;
    }
    if (t >= 128 && t < 160) {
        int k = t - 128;
        float s = 0.f;
#pragma unroll
        for (int m = 0; m < FF; m++) s += wl02[k * FF + m] * wl2[m];
        g_wpack[O_WZ + k] = s;
    }
    if (t == 160) {
        float s = bl2[0];
#pragma unroll
        for (int m = 0; m < FF; m++) s += bl02[m] * wl2[m];
        g_wpack[O_BZ] = s;
    }
}

// ---------------- node projection (unchanged R11 form, smem weights) ----------------
template <int KP>
__global__ __launch_bounds__(256) void k_node(const float* __restrict__ acca,
                                              const float* __restrict__ accb,
                                              const float* __restrict__ W0,
                                              const float* __restrict__ b0) {
    __shared__ __align__(16) float s_w[2 * KP * FF];
    __shared__ __align__(16) float s_b[FF];
    int tid = threadIdx.x;

    int n = blockIdx.x * 128 + (tid & 127);
    float cnt = (n < NN) ? g_cnt[n] : 1.0f;

    cpsh(s_w, W0, 2 * KP * FF, tid, 256);
    cpsh(s_b, b0, FF, tid, 256);
    __syncthreads();

    int isV = tid >> 7;
    if (n >= NN) return;

    float inv = 1.0f / fmaxf(cnt, 1.0f);
    const float* ws = s_w + (isV ? KP * FF : 0);

    V32 acc;
    if (isV) {
#pragma unroll
        for (int j = 0; j < FF; j++) acc.f[j] = 0.f;
    } else {
        ldbias_s(acc, s_b);
    }

    const float* xpa = acca + (size_t)n * FF;
#pragma unroll
    for (int k4 = 0; k4 < 8; k4++) {
        float4 xv = *(const float4*)(xpa + k4 * 4);
        xv.x = fmaxf(xv.x, 0.f) * inv;
        xv.y = fmaxf(xv.y, 0.f) * inv;
        xv.z = fmaxf(xv.z, 0.f) * inv;
        xv.w = fmaxf(xv.w, 0.f) * inv;
        int k = k4 * 4;
        fmarow1(acc, pk2(xv.x), ws + (k + 0) * FF);
        fmarow1(acc, pk2(xv.y), ws + (k + 1) * FF);
        fmarow1(acc, pk2(xv.z), ws + (k + 2) * FF);
        fmarow1(acc, pk2(xv.w), ws + (k + 3) * FF);
    }
    if (KP == 64) {
        const float* xpb = accb + (size_t)n * FF;
#pragma unroll
        for (int k4 = 0; k4 < 8; k4++) {
            float4 xv = *(const float4*)(xpb + k4 * 4);
            xv.x = fmaxf(xv.x, 0.f) * inv;
            xv.y = fmaxf(xv.y, 0.f) * inv;
            xv.z = fmaxf(xv.z, 0.f) * inv;
            xv.w = fmaxf(xv.w, 0.f) * inv;
            int k = 32 + k4 * 4;
            fmarow1(acc, pk2(xv.x), ws + (k + 0) * FF);
            fmarow1(acc, pk2(xv.y), ws + (k + 1) * FF);
            fmarow1(acc, pk2(xv.z), ws + (k + 2) * FF);
            fmarow1(acc, pk2(xv.w), ws + (k + 3) * FF);
        }
    }

    float* up = g_uv + (size_t)n * 64 + isV * 32;
#pragma unroll
    for (int j = 0; j < FF; j += 4) *(float4*)(up + j) = *(float4*)(acc.f + j);
}

// ---------------- conv1 (pair, constant weights, no smem/barrier) ----------------
__global__ __launch_bounds__(128) void k_conv1(const float* __restrict__ ea,
                                               const int* __restrict__ eidx) {
    int p = blockIdx.x * blockDim.x + threadIdx.x;
    if (p >= HALF_E) return;
    int e0 = 2 * p, e1 = 2 * p + 1;

    float4 a0 = *(const float4*)(ea + (size_t)e0 * 4);
    float4 a1 = *(const float4*)(ea + (size_t)e1 * 4);
    int r0 = eidx[e0], r1 = eidx[e1];

    V32 h0, h1;
    ldbiasc(h0, O_B10);
    ldbiasc(h1, O_B10);
    fmarow2c(h0, h1, pk2(a0.x), pk2(a1.x), O_W10);
    fmarow2c(h0, h1, pk2(a0.y), pk2(a1.y), O_W10 + FF);
    fmarow2c(h0, h1, pk2(a0.z), pk2(a1.z), O_W10 + 2 * FF);
    fmarow2c(h0, h1, pk2(a0.w), pk2(a1.w), O_W10 + 3 * FF);
    relu32(h0);
    relu32(h1);

    V32 o0, o1;
    layer2c(o0, o1, h0, h1, O_W11, O_B11);

    scatter32(g_acc1 + (size_t)r0 * FF, o0);
    scatter32(g_acc1 + (size_t)r1 * FF, o1);
    atomicAdd(&g_cnt[r0], 1.0f);
    atomicAdd(&g_cnt[r1], 1.0f);
    store_relu2T(g_e1, e0, o0, o1);
}

// ---------------- edge2 ----------------
__global__ __launch_bounds__(128) void k_edge2(const float* __restrict__ ea,
                                               const int* __restrict__ eidx) {
    int p = blockIdx.x * blockDim.x + threadIdx.x;
    if (p >= HALF_E) return;
    int e0 = 2 * p, e1 = 2 * p + 1;
    int r0 = eidx[e0], c0 = eidx[EE + e0];
    int r1 = eidx[e1], c1 = eidx[EE + e1];

    V32 h0, h1;
    uvinit(h0, r0, c0);
    uvinit(h1, r1, c1);

    float4 a0 = *(const float4*)(ea + (size_t)e0 * 4);
    float4 a1 = *(const float4*)(ea + (size_t)e1 * 4);
    fmarow2c(h0, h1, pk2(a0.x), pk2(a1.x), O_W20E);
    fmarow2c(h0, h1, pk2(a0.y), pk2(a1.y), O_W20E + FF);
    fmarow2c(h0, h1, pk2(a0.z), pk2(a1.z), O_W20E + 2 * FF);
    fmarow2c(h0, h1, pk2(a0.w), pk2(a1.w), O_W20E + 3 * FF);
    seg32pTc(h0, h1, g_e1, e0, O_W20E + 4 * FF);
    relu32(h0);
    relu32(h1);

    V32 o0, o1;
    layer2c(o0, o1, h0, h1, O_W21, O_B21);

    scatter32(g_acc2 + (size_t)r0 * FF, o0);
    scatter32(g_acc2 + (size_t)r1 * FF, o1);
    store_relu2T(g_e2, e0, o0, o1);
}

// ---------------- edge3 ----------------
__global__ __launch_bounds__(128) void k_edge3(const int* __restrict__ eidx) {
    int p = blockIdx.x * blockDim.x + threadIdx.x;
    if (p >= HALF_E) return;
    int e0 = 2 * p, e1 = 2 * p + 1;
    int r0 = eidx[e0], c0 = eidx[EE + e0];
    int r1 = eidx[e1], c1 = eidx[EE + e1];

    V32 h0, h1;
    uvinit(h0, r0, c0);
    uvinit(h1, r1, c1);
    seg32pTc(h0, h1, g_e2, e0, O_W30E);
    seg32pTc(h0, h1, g_e1, e0, O_W30E + 32 * FF);
    relu32(h0);
    relu32(h1);

    V32 o0, o1;
    layer2c(o0, o1, h0, h1, O_W31, O_B31);

    scatter32(g_acc3 + (size_t)r0 * FF, o0);
    scatter32(g_acc3 + (size_t)r1 * FF, o1);
    store_relu2T(g_e3, e0, o0, o1);
}

// ---------------- edge4 + folded heads ----------------
__global__ __launch_bounds__(128) void k_edge4(const float* __restrict__ ea,
                                               const int* __restrict__ eidx,
                                               float* __restrict__ out) {
    int p = blockIdx.x * blockDim.x + threadIdx.x;
    if (p >= HALF_E) return;
    int e0 = 2 * p, e1 = 2 * p + 1;
    int r0 = eidx[e0], c0 = eidx[EE + e0];
    int r1 = eidx[e1], c1 = eidx[EE + e1];

    V32 h0, h1;
    uvinit(h0, r0, c0);
    uvinit(h1, r1, c1);
    seg32pTc(h0, h1, g_e3, e0, O_W40E);
    seg32pTc(h0, h1, g_e2, e0, O_W40E + 32 * FF);
    relu32(h0);
    relu32(h1);

    V32 e40, e41;
    layer2c(e40, e41, h0, h1, O_W41, O_B41);
    relu32(e40);
    relu32(e41);

    float4 a0 = *(const float4*)(ea + (size_t)e0 * 4);
    float4 a1 = *(const float4*)(ea + (size_t)e1 * 4);
    float x00 = c_pack[O_BX + 0] + a0.x, x01 = c_pack[O_BX + 1] + a0.y;
    float x02 = c_pack[O_BX + 2] + a0.z, x03 = c_pack[O_BX + 3] + a0.w;
    float x10 = c_pack[O_BX + 0] + a1.x, x11 = c_pack[O_BX + 1] + a1.y;
    float x12 = c_pack[O_BX + 2] + a1.z, x13 = c_pack[O_BX + 3] + a1.w;
    float z0 = c_pack[O_BZ], z1 = c_pack[O_BZ];
#pragma unroll
    for (int k = 0; k < FF; k++) {
        float4 w = *(const float4*)(c_pack + O_WX + k * 4);
        float wzk = c_pack[O_WZ + k];
        float v0 = e40.f[k], v1 = e41.f[k];
        x00 += v0 * w.x;
        x01 += v0 * w.y;
        x02 += v0 * w.z;
        x03 += v0 * w.w;
        z0 += v0 * wzk;
        x10 += v1 * w.x;
        x11 += v1 * w.y;
        x12 += v1 * w.z;
        x13 += v1 * w.w;
        z1 += v1 * wzk;
    }
    {
        float nrm = sqrtf(x00 * x00 + x01 * x01 + x02 * x02 + x03 * x03);
        float inv = 1.0f / fmaxf(nrm, 1e-12f);
        *(float4*)(out + (size_t)EE + (size_t)e0 * 4) =
            make_float4(x00 * inv, x01 * inv, x02 * inv, x03 * inv);
    }
    {
        float nrm = sqrtf(x10 * x10 + x11 * x11 + x12 * x12 + x13 * x13);
        float inv = 1.0f / fmaxf(nrm, 1e-12f);
        *(float4*)(out + (size_t)EE + (size_t)e1 * 4) =
            make_float4(x10 * inv, x11 * inv, x12 * inv, x13 * inv);
    }
    out[e0] = 1.0f / (1.0f + expf(-z0));
    out[e1] = 1.0f / (1.0f + expf(-z1));
}

// ---------------- launch ----------------
extern "C" void kernel_launch(void* const* d_in, const int* in_sizes, int n_in,
                              void* d_out, int out_size) {
    const int* eidx = (const int*)d_in[1];
    const float* ea = (const float*)d_in[2];
    const float* beta = (const float*)d_in[3];
    const float* w10 = (const float*)d_in[4];
    const float* b10 = (const float*)d_in[5];
    const float* w11 = (const float*)d_in[6];
    const float* b11 = (const float*)d_in[7];
    const float* w20 = (const float*)d_in[8];
    const float* b20 = (const float*)d_in[9];
    const float* w21 = (const float*)d_in[10];
    const float* b21 = (const float*)d_in[11];
    const float* w30 = (const float*)d_in[12];
    const float* b30 = (const float*)d_in[13];
    const float* w31 = (const float*)d_in[14];
    const float* b31 = (const float*)d_in[15];
    const float* w40 = (const float*)d_in[16];
    const float* b40 = (const float*)d_in[17];
    const float* w41 = (const float*)d_in[18];
    const float* b41 = (const float*)d_in[19];
    const float* wl01 = (const float*)d_in[20];
    const float* bl01 = (const float*)d_in[21];
    const float* wl02 = (const float*)d_in[22];
    const float* bl02 = (const float*)d_in[23];
    const float* wl1 = (const float*)d_in[24];
    const float* bl1 = (const float*)d_in[25];
    const float* wl2 = (const float*)d_in[26];
    const float* bl2 = (const float*)d_in[27];
    float* out = (float*)d_out;

    float *acc1p, *acc2p, *acc3p, *wpackp;
    cudaGetSymbolAddress((void**)&acc1p, g_acc1);
    cudaGetSymbolAddress((void**)&acc2p, g_acc2);
    cudaGetSymbolAddress((void**)&acc3p, g_acc3);
    cudaGetSymbolAddress((void**)&wpackp, g_wpack);

    const int T = 256;
    const int gridNF = (NN * FF + T - 1) / T;
    const int TB = 128;
    const int gridP = (HALF_E + TB - 1) / TB;
    const int gridN = (NN + 127) / 128;

    k_init<<<gridNF, T>>>(beta, out);
    k_pack<<<1, 256>>>(w10, b10, w11, b11, w20, w21, b21, w30, w31, b31, w40, w41, b41,
                       wl01, bl01, wl02, bl02, wl1, bl1, wl2, bl2);
    cudaMemcpyToSymbolAsync(c_pack, wpackp, PACK_N * sizeof(float), 0,
                            cudaMemcpyDeviceToDevice, 0);

    k_conv1<<<gridP, TB>>>(ea, eidx);

    k_node<32><<<gridN, 256>>>(acc1p, nullptr, w20, b20);
    k_edge2<<<gridP, TB>>>(ea, eidx);

    k_node<64><<<gridN, 256>>>(acc2p, acc1p, w30, b30);
    k_edge3<<<gridP, TB>>>(eidx);

    k_node<64><<<gridN, 256>>>(acc3p, acc2p, w40, b40);
    k_edge4<<<gridP, TB>>>(ea, eidx, out);
}